// round 9
// baseline (speedup 1.0000x reference)
#include <cuda_runtime.h>
#include <cuda_fp16.h>
#include <cstdint>

#define N_NODES 100000
#define N_EDGES 1600000
#define D 128          // D_IN == D_OUT == 128
#define BIN 64         // slots per row bin; P(degree>64) ~ 5e-19 per row

// ---- device-global scratch (allocation-free rule) ----
__device__ __half g_supph[(size_t)N_NODES * D];     // 25.6 MB fp16 support
__device__ int    g_cur[N_NODES];                   // zero at load; reset by spmm
__device__ int2   g_edge[(size_t)N_NODES * BIN];    // 51.2 MB row bins

// ---- GEMM tiling ----
#define GR 128
#define KT 32
#define XS_S 36    // 32 + 4 pad  (A fragment banks: 4*gid+tig, bijective)
#define WS_S 136   // 128 + 8 pad (B fragment banks: 8*tig+gid, bijective)
#define XS_ELEMS (GR * XS_S)
#define WS_ELEMS (KT * WS_S)
#define STAGE_ELEMS (XS_ELEMS + WS_ELEMS)
#define GEMM_SMEM_BYTES (2 * STAGE_ELEMS * 4)   // 71680 B

__global__ void gemm_tc_kernel(const float*, const float*, const float*);

// ---- side stream + events + func attribute, once per process ----
struct StreamInit {
    cudaStream_t s2;
    cudaEvent_t ev_fork, ev_join;
    StreamInit() {
        cudaStreamCreateWithFlags(&s2, cudaStreamNonBlocking);
        cudaEventCreateWithFlags(&ev_fork, cudaEventDisableTiming);
        cudaEventCreateWithFlags(&ev_join, cudaEventDisableTiming);
        cudaFuncSetAttribute(gemm_tc_kernel,
                             cudaFuncAttributeMaxDynamicSharedMemorySize,
                             GEMM_SMEM_BYTES);
    }
};
static StreamInit g_si;

// ---------------------------------------------------------------------------
// GEMM (tf32 tensor cores, 2-stage cp.async pipeline): support = x@W+b, fp16.
// Unchanged from R8-measured kernel (32.4 us).
// ---------------------------------------------------------------------------
__device__ __forceinline__ unsigned f2tf32(float f) {
    unsigned u;
    asm("cvt.rna.tf32.f32 %0, %1;" : "=r"(u) : "f"(f));
    return u;
}

__device__ __forceinline__ void mma_tf32(float c[4], const unsigned a[4],
                                         const unsigned bb[2]) {
    asm volatile(
        "mma.sync.aligned.m16n8k8.row.col.f32.tf32.tf32.f32 "
        "{%0,%1,%2,%3}, {%4,%5,%6,%7}, {%8,%9}, {%0,%1,%2,%3};"
        : "+f"(c[0]), "+f"(c[1]), "+f"(c[2]), "+f"(c[3])
        : "r"(a[0]), "r"(a[1]), "r"(a[2]), "r"(a[3]),
          "r"(bb[0]), "r"(bb[1]));
}

__device__ __forceinline__ void cpa16(void* smem_dst, const void* gmem_src,
                                      bool pred) {
    unsigned sa = (unsigned)__cvta_generic_to_shared(smem_dst);
    int sz = pred ? 16 : 0;
    asm volatile("cp.async.cg.shared.global [%0], [%1], 16, %2;"
                 :: "r"(sa), "l"(gmem_src), "r"(sz));
}

__global__ __launch_bounds__(256, 2) void gemm_tc_kernel(
    const float* __restrict__ x, const float* __restrict__ W,
    const float* __restrict__ b) {
    extern __shared__ float smem[];
#define XS(st, r, k) smem[(st) * STAGE_ELEMS + (r) * XS_S + (k)]
#define WS(st, k, c) smem[(st) * STAGE_ELEMS + XS_ELEMS + (k) * WS_S + (c)]

    const int tid  = threadIdx.x;
    const int lane = tid & 31;
    const int warp = tid >> 5;
    const int wr   = warp >> 1;
    const int wc   = warp & 1;
    const int gid  = lane >> 2;
    const int tig  = lane & 3;
    const int row0 = blockIdx.x * GR;

    auto prefetch = [&](int st, int kt) {
#pragma unroll
        for (int j = 0; j < 4; j++) {
            int id = tid + j * 256;
            int r = id >> 3, c16 = id & 7;
            int grow = row0 + r;
            bool ok = grow < N_NODES;
            const float* src = x + (size_t)(ok ? grow : 0) * D + kt + c16 * 4;
            cpa16(&XS(st, r, c16 * 4), src, ok);
        }
#pragma unroll
        for (int j = 0; j < 4; j++) {
            int id = tid + j * 256;
            int k = id >> 5, c16 = id & 31;
            cpa16(&WS(st, k, c16 * 4), W + (size_t)(kt + k) * D + c16 * 4, true);
        }
        asm volatile("cp.async.commit_group;");
    };

    float acc[2][8][4];
#pragma unroll
    for (int mi = 0; mi < 2; mi++)
#pragma unroll
        for (int ni = 0; ni < 8; ni++)
#pragma unroll
            for (int q = 0; q < 4; q++) acc[mi][ni][q] = 0.f;

    prefetch(0, 0);

#pragma unroll
    for (int kti = 0; kti < 4; kti++) {
        if (kti < 3) {
            prefetch((kti + 1) & 1, (kti + 1) * KT);
            asm volatile("cp.async.wait_group 1;" ::: "memory");
        } else {
            asm volatile("cp.async.wait_group 0;" ::: "memory");
        }
        __syncthreads();

        const int st = kti & 1;
#pragma unroll
        for (int ks = 0; ks < 4; ks++) {
            const int kb = ks * 8;
            unsigned a[2][4];
#pragma unroll
            for (int mi = 0; mi < 2; mi++) {
                const int r = wr * 32 + mi * 16 + gid;
                a[mi][0] = f2tf32(XS(st, r, kb + tig));
                a[mi][1] = f2tf32(XS(st, r + 8, kb + tig));
                a[mi][2] = f2tf32(XS(st, r, kb + tig + 4));
                a[mi][3] = f2tf32(XS(st, r + 8, kb + tig + 4));
            }
            unsigned bb[8][2];
#pragma unroll
            for (int ni = 0; ni < 8; ni++) {
                const int c = wc * 64 + ni * 8 + gid;
                bb[ni][0] = f2tf32(WS(st, kb + tig, c));
                bb[ni][1] = f2tf32(WS(st, kb + tig + 4, c));
            }
#pragma unroll
            for (int mi = 0; mi < 2; mi++)
#pragma unroll
                for (int ni = 0; ni < 8; ni++)
                    mma_tf32(acc[mi][ni], a[mi], bb[ni]);
        }
        __syncthreads();
    }

#pragma unroll
    for (int mi = 0; mi < 2; mi++) {
#pragma unroll
        for (int ni = 0; ni < 8; ni++) {
            const int col = wc * 64 + ni * 8 + 2 * tig;
            const float b0 = b[col], b1 = b[col + 1];
            const int r0 = row0 + wr * 32 + mi * 16 + gid;
            const int r1 = r0 + 8;
            if (r0 < N_NODES) {
                __half2 h = __floats2half2_rn(acc[mi][ni][0] + b0,
                                              acc[mi][ni][1] + b1);
                *reinterpret_cast<__half2*>(&g_supph[(size_t)r0 * D + col]) = h;
            }
            if (r1 < N_NODES) {
                __half2 h = __floats2half2_rn(acc[mi][ni][2] + b0,
                                              acc[mi][ni][3] + b1);
                *reinterpret_cast<__half2*>(&g_supph[(size_t)r1 * D + col]) = h;
            }
        }
    }
#undef XS
#undef WS
}

// ---------------------------------------------------------------------------
// Binning (replaces hist+scan+fill): one pass, fixed 64-slot row bins.
// g_cur starts zero (module load / reset by spmm each call).
// ---------------------------------------------------------------------------
__global__ void fill_direct_kernel(const int* __restrict__ rows,
                                   const int* __restrict__ cols,
                                   const float* __restrict__ vals) {
    int e = blockIdx.x * blockDim.x + threadIdx.x;
    if (e >= N_EDGES) return;
    int r = rows[e];
    int pos = atomicAdd(&g_cur[r], 1);
    if (pos < BIN)   // unreachable for this distribution; guards OOB
        g_edge[(size_t)r * BIN + pos] = make_int2(cols[e],
                                                  __float_as_int(vals[e]));
}

// ---------------------------------------------------------------------------
// SpMM: one warp per output row, fixed-stride bin, fp16 gathers (256B/row),
//       fp32 accumulate, float4 store. Resets g_cur for the next replay.
// ---------------------------------------------------------------------------
__global__ __launch_bounds__(256) void spmm_kernel(float* __restrict__ out) {
    const int row  = (blockIdx.x * blockDim.x + threadIdx.x) >> 5;
    const int lane = threadIdx.x & 31;
    if (row >= N_NODES) return;

    int cnt = g_cur[row];
    if (cnt > BIN) cnt = BIN;
    __syncwarp();
    if (lane == 0) g_cur[row] = 0;       // deterministic post-state

    const int2* eb = g_edge + (size_t)row * BIN;
    float4 acc = make_float4(0.f, 0.f, 0.f, 0.f);

    int i = 0;
    for (; i + 3 < cnt; i += 4) {
        int2 e0 = __ldg(&eb[i]);
        int2 e1 = __ldg(&eb[i + 1]);
        int2 e2 = __ldg(&eb[i + 2]);
        int2 e3 = __ldg(&eb[i + 3]);
        uint2 h0 = *reinterpret_cast<const uint2*>(
            &g_supph[(size_t)e0.x * D + lane * 4]);
        uint2 h1 = *reinterpret_cast<const uint2*>(
            &g_supph[(size_t)e1.x * D + lane * 4]);
        uint2 h2 = *reinterpret_cast<const uint2*>(
            &g_supph[(size_t)e2.x * D + lane * 4]);
        uint2 h3 = *reinterpret_cast<const uint2*>(
            &g_supph[(size_t)e3.x * D + lane * 4]);
        float v0 = __int_as_float(e0.y), v1 = __int_as_float(e1.y);
        float v2 = __int_as_float(e2.y), v3 = __int_as_float(e3.y);
        float2 a0 = __half22float2(*reinterpret_cast<__half2*>(&h0.x));
        float2 b0 = __half22float2(*reinterpret_cast<__half2*>(&h0.y));
        float2 a1 = __half22float2(*reinterpret_cast<__half2*>(&h1.x));
        float2 b1 = __half22float2(*reinterpret_cast<__half2*>(&h1.y));
        float2 a2 = __half22float2(*reinterpret_cast<__half2*>(&h2.x));
        float2 b2 = __half22float2(*reinterpret_cast<__half2*>(&h2.y));
        float2 a3 = __half22float2(*reinterpret_cast<__half2*>(&h3.x));
        float2 b3 = __half22float2(*reinterpret_cast<__half2*>(&h3.y));
        acc.x += a0.x * v0; acc.y += a0.y * v0;
        acc.z += b0.x * v0; acc.w += b0.y * v0;
        acc.x += a1.x * v1; acc.y += a1.y * v1;
        acc.z += b1.x * v1; acc.w += b1.y * v1;
        acc.x += a2.x * v2; acc.y += a2.y * v2;
        acc.z += b2.x * v2; acc.w += b2.y * v2;
        acc.x += a3.x * v3; acc.y += a3.y * v3;
        acc.z += b3.x * v3; acc.w += b3.y * v3;
    }
    for (; i < cnt; i++) {
        int2 e0 = __ldg(&eb[i]);
        float v0 = __int_as_float(e0.y);
        uint2 h0 = *reinterpret_cast<const uint2*>(
            &g_supph[(size_t)e0.x * D + lane * 4]);
        float2 a0 = __half22float2(*reinterpret_cast<__half2*>(&h0.x));
        float2 b0 = __half22float2(*reinterpret_cast<__half2*>(&h0.y));
        acc.x += a0.x * v0; acc.y += a0.y * v0;
        acc.z += b0.x * v0; acc.w += b0.y * v0;
    }
    reinterpret_cast<float4*>(out)[(size_t)row * (D / 4) + lane] = acc;
}

// ---------------------------------------------------------------------------
// Launch. Inputs: x, rows, cols, vals, W, b.  Output: f32 [N_NODES, D].
// Fork-join: binning on side stream || pipelined GEMM on capture stream;
// join; SpMM. 4 kernels total.
// ---------------------------------------------------------------------------
extern "C" void kernel_launch(void* const* d_in, const int* in_sizes, int n_in,
                              void* d_out, int out_size) {
    const float* x    = (const float*)d_in[0];
    const int*   rows = (const int*)d_in[1];
    const int*   cols = (const int*)d_in[2];
    const float* vals = (const float*)d_in[3];
    const float* W    = (const float*)d_in[4];
    const float* b    = (const float*)d_in[5];
    float* out = (float*)d_out;

    cudaEventRecord(g_si.ev_fork, 0);
    cudaStreamWaitEvent(g_si.s2, g_si.ev_fork, 0);

    // --- binning on side stream (1 kernel) ---
    fill_direct_kernel<<<(N_EDGES + 255) / 256, 256, 0, g_si.s2>>>(rows, cols,
                                                                   vals);
    cudaEventRecord(g_si.ev_join, g_si.s2);

    // --- GEMM on the capture stream (overlaps binning) ---
    gemm_tc_kernel<<<(N_NODES + GR - 1) / GR, 256, GEMM_SMEM_BYTES>>>(x, W, b);

    // --- join, then SpMM ---
    cudaStreamWaitEvent(0, g_si.ev_join, 0);
    {
        long long total_threads = (long long)N_NODES * 32;
        int blk = 256;
        int grid = (int)((total_threads + blk - 1) / blk);
        spmm_kernel<<<grid, blk>>>(out);
    }
}

// round 10
// speedup vs baseline: 2.0924x; 2.0924x over previous
#include <cuda_runtime.h>
#include <cuda_fp16.h>
#include <cstdint>

#define N_NODES 100000
#define N_EDGES 1600000
#define D 128          // D_IN == D_OUT == 128

#define SCAN_BLK 512
#define NB_SCAN ((N_NODES + SCAN_BLK - 1) / SCAN_BLK)   // 196

// ---- device-global scratch (allocation-free rule) ----
__device__ __half g_supph[(size_t)N_NODES * D];    // 25.6 MB (fp16 support)
__device__ int    g_counts[N_NODES];               // zero at load; re-zeroed by fill
__device__ int    g_rowstart[N_NODES + 1];
__device__ int    g_cur[N_NODES];
__device__ unsigned long long g_status[NB_SCAN];   // lookback flags; re-zeroed by fill
__device__ int2   g_edge[N_EDGES];                 // 12.8 MB packed {col, val bits}

#define FLG_A (1ull << 40)
#define FLG_P (2ull << 40)
#define VAL_MASK 0xFFFFFFFFull

// ---- GEMM tiling ----
#define GR 128
#define KT 32
#define XS_S 36    // 32 + 4 pad  (A fragment banks: 4*gid+tig, bijective)
#define WS_S 136   // 128 + 8 pad (B fragment banks: 8*tig+gid, bijective)
#define XS_ELEMS (GR * XS_S)
#define WS_ELEMS (KT * WS_S)
#define STAGE_ELEMS (XS_ELEMS + WS_ELEMS)
#define GEMM_SMEM_BYTES (2 * STAGE_ELEMS * 4)   // 71680 B

__global__ void gemm_tc_kernel(const float*, const float*, const float*);

// ---- side stream + events + func attribute, once per process ----
struct StreamInit {
    cudaStream_t s2;
    cudaEvent_t ev_fork, ev_join;
    StreamInit() {
        cudaStreamCreateWithFlags(&s2, cudaStreamNonBlocking);
        cudaEventCreateWithFlags(&ev_fork, cudaEventDisableTiming);
        cudaEventCreateWithFlags(&ev_join, cudaEventDisableTiming);
        cudaFuncSetAttribute(gemm_tc_kernel,
                             cudaFuncAttributeMaxDynamicSharedMemorySize,
                             GEMM_SMEM_BYTES);
    }
};
static StreamInit g_si;

// ---------------------------------------------------------------------------
// GEMM (tf32 tensor cores, 2-stage cp.async pipeline): support = x@W+b, fp16.
// Unchanged from R8-measured kernel (32.4 us).
// ---------------------------------------------------------------------------
__device__ __forceinline__ unsigned f2tf32(float f) {
    unsigned u;
    asm("cvt.rna.tf32.f32 %0, %1;" : "=r"(u) : "f"(f));
    return u;
}

__device__ __forceinline__ void mma_tf32(float c[4], const unsigned a[4],
                                         const unsigned bb[2]) {
    asm volatile(
        "mma.sync.aligned.m16n8k8.row.col.f32.tf32.tf32.f32 "
        "{%0,%1,%2,%3}, {%4,%5,%6,%7}, {%8,%9}, {%0,%1,%2,%3};"
        : "+f"(c[0]), "+f"(c[1]), "+f"(c[2]), "+f"(c[3])
        : "r"(a[0]), "r"(a[1]), "r"(a[2]), "r"(a[3]),
          "r"(bb[0]), "r"(bb[1]));
}

__device__ __forceinline__ void cpa16(void* smem_dst, const void* gmem_src,
                                      bool pred) {
    unsigned sa = (unsigned)__cvta_generic_to_shared(smem_dst);
    int sz = pred ? 16 : 0;
    asm volatile("cp.async.cg.shared.global [%0], [%1], 16, %2;"
                 :: "r"(sa), "l"(gmem_src), "r"(sz));
}

__global__ __launch_bounds__(256, 2) void gemm_tc_kernel(
    const float* __restrict__ x, const float* __restrict__ W,
    const float* __restrict__ b) {
    extern __shared__ float smem[];
#define XS(st, r, k) smem[(st) * STAGE_ELEMS + (r) * XS_S + (k)]
#define WS(st, k, c) smem[(st) * STAGE_ELEMS + XS_ELEMS + (k) * WS_S + (c)]

    const int tid  = threadIdx.x;
    const int lane = tid & 31;
    const int warp = tid >> 5;
    const int wr   = warp >> 1;
    const int wc   = warp & 1;
    const int gid  = lane >> 2;
    const int tig  = lane & 3;
    const int row0 = blockIdx.x * GR;

    auto prefetch = [&](int st, int kt) {
#pragma unroll
        for (int j = 0; j < 4; j++) {
            int id = tid + j * 256;
            int r = id >> 3, c16 = id & 7;
            int grow = row0 + r;
            bool ok = grow < N_NODES;
            const float* src = x + (size_t)(ok ? grow : 0) * D + kt + c16 * 4;
            cpa16(&XS(st, r, c16 * 4), src, ok);
        }
#pragma unroll
        for (int j = 0; j < 4; j++) {
            int id = tid + j * 256;
            int k = id >> 5, c16 = id & 31;
            cpa16(&WS(st, k, c16 * 4), W + (size_t)(kt + k) * D + c16 * 4, true);
        }
        asm volatile("cp.async.commit_group;");
    };

    float acc[2][8][4];
#pragma unroll
    for (int mi = 0; mi < 2; mi++)
#pragma unroll
        for (int ni = 0; ni < 8; ni++)
#pragma unroll
            for (int q = 0; q < 4; q++) acc[mi][ni][q] = 0.f;

    prefetch(0, 0);

#pragma unroll
    for (int kti = 0; kti < 4; kti++) {
        if (kti < 3) {
            prefetch((kti + 1) & 1, (kti + 1) * KT);
            asm volatile("cp.async.wait_group 1;" ::: "memory");
        } else {
            asm volatile("cp.async.wait_group 0;" ::: "memory");
        }
        __syncthreads();

        const int st = kti & 1;
#pragma unroll
        for (int ks = 0; ks < 4; ks++) {
            const int kb = ks * 8;
            unsigned a[2][4];
#pragma unroll
            for (int mi = 0; mi < 2; mi++) {
                const int r = wr * 32 + mi * 16 + gid;
                a[mi][0] = f2tf32(XS(st, r, kb + tig));
                a[mi][1] = f2tf32(XS(st, r + 8, kb + tig));
                a[mi][2] = f2tf32(XS(st, r, kb + tig + 4));
                a[mi][3] = f2tf32(XS(st, r + 8, kb + tig + 4));
            }
            unsigned bb[8][2];
#pragma unroll
            for (int ni = 0; ni < 8; ni++) {
                const int c = wc * 64 + ni * 8 + gid;
                bb[ni][0] = f2tf32(WS(st, kb + tig, c));
                bb[ni][1] = f2tf32(WS(st, kb + tig + 4, c));
            }
#pragma unroll
            for (int mi = 0; mi < 2; mi++)
#pragma unroll
                for (int ni = 0; ni < 8; ni++)
                    mma_tf32(acc[mi][ni], a[mi], bb[ni]);
        }
        __syncthreads();
    }

#pragma unroll
    for (int mi = 0; mi < 2; mi++) {
#pragma unroll
        for (int ni = 0; ni < 8; ni++) {
            const int col = wc * 64 + ni * 8 + 2 * tig;
            const float b0 = b[col], b1 = b[col + 1];
            const int r0 = row0 + wr * 32 + mi * 16 + gid;
            const int r1 = r0 + 8;
            if (r0 < N_NODES) {
                __half2 h = __floats2half2_rn(acc[mi][ni][0] + b0,
                                              acc[mi][ni][1] + b1);
                *reinterpret_cast<__half2*>(&g_supph[(size_t)r0 * D + col]) = h;
            }
            if (r1 < N_NODES) {
                __half2 h = __floats2half2_rn(acc[mi][ni][2] + b0,
                                              acc[mi][ni][3] + b1);
                *reinterpret_cast<__half2*>(&g_supph[(size_t)r1 * D + col]) = h;
            }
        }
    }
#undef XS
#undef WS
}

// ---------------------------------------------------------------------------
// CSR chain (3 kernels): hist -> lookback scan -> fill(+cleanup)
// ---------------------------------------------------------------------------
__global__ void hist_kernel(const int* __restrict__ rows) {
    int e = blockIdx.x * blockDim.x + threadIdx.x;
    if (e < N_EDGES) atomicAdd(&g_counts[rows[e]], 1);
}

__global__ void scan_lookback_kernel() {
    __shared__ int sh[SCAN_BLK];
    __shared__ int s_base;
    const int bkt = blockIdx.x;
    const int tid = threadIdx.x;
    const int g = bkt * SCAN_BLK + tid;
    int v = (g < N_NODES) ? g_counts[g] : 0;
    sh[tid] = v;
    __syncthreads();
#pragma unroll
    for (int d = 1; d < SCAN_BLK; d <<= 1) {
        int t = (tid >= d) ? sh[tid - d] : 0;
        __syncthreads();
        sh[tid] += t;
        __syncthreads();
    }
    const int incl = sh[tid];
    const int total = sh[SCAN_BLK - 1];

    if (tid == 0) {
        if (bkt == 0) {
            atomicExch(&g_status[0], FLG_P | (unsigned long long)total);
            s_base = 0;
        } else {
            atomicExch(&g_status[bkt], FLG_A | (unsigned long long)total);
            long long run = 0;
            int p = bkt - 1;
            while (true) {
                unsigned long long s = atomicAdd(&g_status[p], 0ull);
                if (s & (FLG_A | FLG_P)) {
                    run += (long long)(s & VAL_MASK);
                    if (s & FLG_P) break;
                    p--;
                }
            }
            atomicExch(&g_status[bkt],
                       FLG_P | (unsigned long long)(run + total));
            s_base = (int)run;
        }
    }
    __syncthreads();

    const int base = s_base;
    if (g < N_NODES) {
        int st = base + incl - v;     // exclusive
        g_rowstart[g] = st;
        g_cur[g] = st;
        if (g == N_NODES - 1) g_rowstart[N_NODES] = base + incl;
    }
}

__global__ void fill_kernel(const int* __restrict__ rows,
                            const int* __restrict__ cols,
                            const float* __restrict__ vals) {
    int e = blockIdx.x * blockDim.x + threadIdx.x;
    if (e < N_EDGES) {
        int r = rows[e];
        int pos = atomicAdd(&g_cur[r], 1);
        g_edge[pos] = make_int2(cols[e], __float_as_int(vals[e]));
    }
    // cleanup for the next call (deterministic post-state)
    if (e < N_NODES) g_counts[e] = 0;
    if (e < NB_SCAN) g_status[e] = 0ull;
}

// ---------------------------------------------------------------------------
// SpMM v2: one warp per output row. Coalesced edge prefetch (lane i loads
// edge s+i: one 128B load fetches up to 32 edges) + shfl fan-out, so the
// ~16 support gathers issue back-to-back (MLP ~= degree). fp32 accumulate,
// single coalesced float4 store.
// ---------------------------------------------------------------------------
__global__ __launch_bounds__(256) void spmm_kernel(float* __restrict__ out) {
    const int row  = (blockIdx.x * blockDim.x + threadIdx.x) >> 5;
    const int lane = threadIdx.x & 31;
    if (row >= N_NODES) return;

    int s = __ldg(&g_rowstart[row]);
    const int e = __ldg(&g_rowstart[row + 1]);

    float4 acc = make_float4(0.f, 0.f, 0.f, 0.f);

    while (s < e) {
        const int n = min(e - s, 32);
        int2 ed = make_int2(0, 0);
        if (s + lane < e) ed = __ldg(&g_edge[s + lane]);   // coalesced

        for (int j = 0; j < n; j++) {
            const int   c = __shfl_sync(0xffffffffu, ed.x, j);
            const float v = __int_as_float(__shfl_sync(0xffffffffu, ed.y, j));
            uint2 h = *reinterpret_cast<const uint2*>(
                &g_supph[(size_t)c * D + lane * 4]);
            float2 a = __half22float2(*reinterpret_cast<__half2*>(&h.x));
            float2 q = __half22float2(*reinterpret_cast<__half2*>(&h.y));
            acc.x += a.x * v; acc.y += a.y * v;
            acc.z += q.x * v; acc.w += q.y * v;
        }
        s += n;
    }
    reinterpret_cast<float4*>(out)[(size_t)row * (D / 4) + lane] = acc;
}

// ---------------------------------------------------------------------------
// Launch. Inputs: x, rows, cols, vals, W, b.  Output: f32 [N_NODES, D].
// Fork-join: 3-kernel CSR chain on side stream || pipelined GEMM on capture
// stream; join; SpMM.
// ---------------------------------------------------------------------------
extern "C" void kernel_launch(void* const* d_in, const int* in_sizes, int n_in,
                              void* d_out, int out_size) {
    const float* x    = (const float*)d_in[0];
    const int*   rows = (const int*)d_in[1];
    const int*   cols = (const int*)d_in[2];
    const float* vals = (const float*)d_in[3];
    const float* W    = (const float*)d_in[4];
    const float* b    = (const float*)d_in[5];
    float* out = (float*)d_out;

    cudaEventRecord(g_si.ev_fork, 0);
    cudaStreamWaitEvent(g_si.s2, g_si.ev_fork, 0);

    // --- CSR build chain on side stream (3 kernels) ---
    hist_kernel<<<(N_EDGES + 255) / 256, 256, 0, g_si.s2>>>(rows);
    scan_lookback_kernel<<<NB_SCAN, SCAN_BLK, 0, g_si.s2>>>();
    fill_kernel<<<(N_EDGES + 255) / 256, 256, 0, g_si.s2>>>(rows, cols, vals);
    cudaEventRecord(g_si.ev_join, g_si.s2);

    // --- GEMM on the capture stream (overlaps the chain) ---
    gemm_tc_kernel<<<(N_NODES + GR - 1) / GR, 256, GEMM_SMEM_BYTES>>>(x, W, b);

    // --- join, then SpMM ---
    cudaStreamWaitEvent(0, g_si.ev_join, 0);
    {
        long long total_threads = (long long)N_NODES * 32;
        int blk = 256;
        int grid = (int)((total_threads + blk - 1) / blk);
        spmm_kernel<<<grid, blk>>>(out);
    }
}

// round 11
// speedup vs baseline: 2.3093x; 1.1037x over previous
#include <cuda_runtime.h>
#include <cuda_fp16.h>
#include <cstdint>

#define N_NODES 100000
#define N_EDGES 1600000
#define D 128          // D_IN == D_OUT == 128

#define SCAN_BLK 512
#define NB_SCAN ((N_NODES + SCAN_BLK - 1) / SCAN_BLK)   // 196

// ---- device-global scratch (allocation-free rule) ----
__device__ __half g_supph[(size_t)N_NODES * D];    // 25.6 MB (fp16 support)
__device__ int    g_counts[N_NODES];               // zero at load; re-zeroed by fill
__device__ int    g_rowstart[N_NODES + 1];
__device__ int    g_cur[N_NODES];
__device__ unsigned long long g_status[NB_SCAN];   // lookback flags; re-zeroed by fill
__device__ int2   g_edge[N_EDGES];                 // 12.8 MB packed {col, val bits}

#define FLG_A (1ull << 40)
#define FLG_P (2ull << 40)
#define VAL_MASK 0xFFFFFFFFull

// ---- GEMM tiling ----
#define GR 128
#define KT 32
#define XS_S 36    // 32 + 4 pad  (A fragment banks: 4*gid+tig, bijective)
#define WS_S 136   // 128 + 8 pad (B fragment banks: 8*tig+gid, bijective)
#define XS_ELEMS (GR * XS_S)
#define WS_ELEMS (KT * WS_S)
#define STAGE_ELEMS (XS_ELEMS + WS_ELEMS)
#define GEMM_SMEM_BYTES (2 * STAGE_ELEMS * 4)   // 71680 B

__global__ void gemm_tc_kernel(const float*, const float*, const float*);

// ---- side stream + events + func attribute, once per process ----
struct StreamInit {
    cudaStream_t s2;
    cudaEvent_t ev_fork, ev_join;
    StreamInit() {
        cudaStreamCreateWithFlags(&s2, cudaStreamNonBlocking);
        cudaEventCreateWithFlags(&ev_fork, cudaEventDisableTiming);
        cudaEventCreateWithFlags(&ev_join, cudaEventDisableTiming);
        cudaFuncSetAttribute(gemm_tc_kernel,
                             cudaFuncAttributeMaxDynamicSharedMemorySize,
                             GEMM_SMEM_BYTES);
    }
};
static StreamInit g_si;

// ---------------------------------------------------------------------------
// GEMM (tf32 tensor cores, 2-stage cp.async pipeline): support = x@W+b, fp16.
// Unchanged from R8/R10-measured kernel (32.2 us).
// ---------------------------------------------------------------------------
__device__ __forceinline__ unsigned f2tf32(float f) {
    unsigned u;
    asm("cvt.rna.tf32.f32 %0, %1;" : "=r"(u) : "f"(f));
    return u;
}

__device__ __forceinline__ void mma_tf32(float c[4], const unsigned a[4],
                                         const unsigned bb[2]) {
    asm volatile(
        "mma.sync.aligned.m16n8k8.row.col.f32.tf32.tf32.f32 "
        "{%0,%1,%2,%3}, {%4,%5,%6,%7}, {%8,%9}, {%0,%1,%2,%3};"
        : "+f"(c[0]), "+f"(c[1]), "+f"(c[2]), "+f"(c[3])
        : "r"(a[0]), "r"(a[1]), "r"(a[2]), "r"(a[3]),
          "r"(bb[0]), "r"(bb[1]));
}

__device__ __forceinline__ void cpa16(void* smem_dst, const void* gmem_src,
                                      bool pred) {
    unsigned sa = (unsigned)__cvta_generic_to_shared(smem_dst);
    int sz = pred ? 16 : 0;
    asm volatile("cp.async.cg.shared.global [%0], [%1], 16, %2;"
                 :: "r"(sa), "l"(gmem_src), "r"(sz));
}

__global__ __launch_bounds__(256, 2) void gemm_tc_kernel(
    const float* __restrict__ x, const float* __restrict__ W,
    const float* __restrict__ b) {
    extern __shared__ float smem[];
#define XS(st, r, k) smem[(st) * STAGE_ELEMS + (r) * XS_S + (k)]
#define WS(st, k, c) smem[(st) * STAGE_ELEMS + XS_ELEMS + (k) * WS_S + (c)]

    const int tid  = threadIdx.x;
    const int lane = tid & 31;
    const int warp = tid >> 5;
    const int wr   = warp >> 1;
    const int wc   = warp & 1;
    const int gid  = lane >> 2;
    const int tig  = lane & 3;
    const int row0 = blockIdx.x * GR;

    auto prefetch = [&](int st, int kt) {
#pragma unroll
        for (int j = 0; j < 4; j++) {
            int id = tid + j * 256;
            int r = id >> 3, c16 = id & 7;
            int grow = row0 + r;
            bool ok = grow < N_NODES;
            const float* src = x + (size_t)(ok ? grow : 0) * D + kt + c16 * 4;
            cpa16(&XS(st, r, c16 * 4), src, ok);
        }
#pragma unroll
        for (int j = 0; j < 4; j++) {
            int id = tid + j * 256;
            int k = id >> 5, c16 = id & 31;
            cpa16(&WS(st, k, c16 * 4), W + (size_t)(kt + k) * D + c16 * 4, true);
        }
        asm volatile("cp.async.commit_group;");
    };

    float acc[2][8][4];
#pragma unroll
    for (int mi = 0; mi < 2; mi++)
#pragma unroll
        for (int ni = 0; ni < 8; ni++)
#pragma unroll
            for (int q = 0; q < 4; q++) acc[mi][ni][q] = 0.f;

    prefetch(0, 0);

#pragma unroll
    for (int kti = 0; kti < 4; kti++) {
        if (kti < 3) {
            prefetch((kti + 1) & 1, (kti + 1) * KT);
            asm volatile("cp.async.wait_group 1;" ::: "memory");
        } else {
            asm volatile("cp.async.wait_group 0;" ::: "memory");
        }
        __syncthreads();

        const int st = kti & 1;
#pragma unroll
        for (int ks = 0; ks < 4; ks++) {
            const int kb = ks * 8;
            unsigned a[2][4];
#pragma unroll
            for (int mi = 0; mi < 2; mi++) {
                const int r = wr * 32 + mi * 16 + gid;
                a[mi][0] = f2tf32(XS(st, r, kb + tig));
                a[mi][1] = f2tf32(XS(st, r + 8, kb + tig));
                a[mi][2] = f2tf32(XS(st, r, kb + tig + 4));
                a[mi][3] = f2tf32(XS(st, r + 8, kb + tig + 4));
            }
            unsigned bb[8][2];
#pragma unroll
            for (int ni = 0; ni < 8; ni++) {
                const int c = wc * 64 + ni * 8 + gid;
                bb[ni][0] = f2tf32(WS(st, kb + tig, c));
                bb[ni][1] = f2tf32(WS(st, kb + tig + 4, c));
            }
#pragma unroll
            for (int mi = 0; mi < 2; mi++)
#pragma unroll
                for (int ni = 0; ni < 8; ni++)
                    mma_tf32(acc[mi][ni], a[mi], bb[ni]);
        }
        __syncthreads();
    }

#pragma unroll
    for (int mi = 0; mi < 2; mi++) {
#pragma unroll
        for (int ni = 0; ni < 8; ni++) {
            const int col = wc * 64 + ni * 8 + 2 * tig;
            const float b0 = b[col], b1 = b[col + 1];
            const int r0 = row0 + wr * 32 + mi * 16 + gid;
            const int r1 = r0 + 8;
            if (r0 < N_NODES) {
                __half2 h = __floats2half2_rn(acc[mi][ni][0] + b0,
                                              acc[mi][ni][1] + b1);
                *reinterpret_cast<__half2*>(&g_supph[(size_t)r0 * D + col]) = h;
            }
            if (r1 < N_NODES) {
                __half2 h = __floats2half2_rn(acc[mi][ni][2] + b0,
                                              acc[mi][ni][3] + b1);
                *reinterpret_cast<__half2*>(&g_supph[(size_t)r1 * D + col]) = h;
            }
        }
    }
#undef XS
#undef WS
}

// ---------------------------------------------------------------------------
// CSR chain (3 kernels): hist -> lookback scan -> fill(+cleanup)
// hist/fill vectorized: 4 edges per thread via 128-bit loads.
// ---------------------------------------------------------------------------
__global__ void hist_kernel(const int4* __restrict__ rows4) {
    int i = blockIdx.x * blockDim.x + threadIdx.x;
    if (i < N_EDGES / 4) {
        int4 r = __ldg(&rows4[i]);
        atomicAdd(&g_counts[r.x], 1);
        atomicAdd(&g_counts[r.y], 1);
        atomicAdd(&g_counts[r.z], 1);
        atomicAdd(&g_counts[r.w], 1);
    }
}

__global__ void scan_lookback_kernel() {
    __shared__ int sh[SCAN_BLK];
    __shared__ int s_base;
    const int bkt = blockIdx.x;
    const int tid = threadIdx.x;
    const int g = bkt * SCAN_BLK + tid;
    int v = (g < N_NODES) ? g_counts[g] : 0;
    sh[tid] = v;
    __syncthreads();
#pragma unroll
    for (int d = 1; d < SCAN_BLK; d <<= 1) {
        int t = (tid >= d) ? sh[tid - d] : 0;
        __syncthreads();
        sh[tid] += t;
        __syncthreads();
    }
    const int incl = sh[tid];
    const int total = sh[SCAN_BLK - 1];

    if (tid == 0) {
        if (bkt == 0) {
            atomicExch(&g_status[0], FLG_P | (unsigned long long)total);
            s_base = 0;
        } else {
            atomicExch(&g_status[bkt], FLG_A | (unsigned long long)total);
            long long run = 0;
            int p = bkt - 1;
            while (true) {
                unsigned long long s = atomicAdd(&g_status[p], 0ull);
                if (s & (FLG_A | FLG_P)) {
                    run += (long long)(s & VAL_MASK);
                    if (s & FLG_P) break;
                    p--;
                }
            }
            atomicExch(&g_status[bkt],
                       FLG_P | (unsigned long long)(run + total));
            s_base = (int)run;
        }
    }
    __syncthreads();

    const int base = s_base;
    if (g < N_NODES) {
        int st = base + incl - v;     // exclusive
        g_rowstart[g] = st;
        g_cur[g] = st;
        if (g == N_NODES - 1) g_rowstart[N_NODES] = base + incl;
    }
}

__global__ void fill_kernel(const int4* __restrict__ rows4,
                            const int4* __restrict__ cols4,
                            const float4* __restrict__ vals4) {
    int i = blockIdx.x * blockDim.x + threadIdx.x;
    if (i < N_EDGES / 4) {
        int4 r = __ldg(&rows4[i]);
        int4 c = __ldg(&cols4[i]);
        float4 v = __ldg(&vals4[i]);
        int p0 = atomicAdd(&g_cur[r.x], 1);
        int p1 = atomicAdd(&g_cur[r.y], 1);
        int p2 = atomicAdd(&g_cur[r.z], 1);
        int p3 = atomicAdd(&g_cur[r.w], 1);
        g_edge[p0] = make_int2(c.x, __float_as_int(v.x));
        g_edge[p1] = make_int2(c.y, __float_as_int(v.y));
        g_edge[p2] = make_int2(c.z, __float_as_int(v.z));
        g_edge[p3] = make_int2(c.w, __float_as_int(v.w));
    }
    // cleanup for the next call (grid covers N_EDGES/4 = 400k >= N_NODES)
    if (i < N_NODES) g_counts[i] = 0;
    if (i < NB_SCAN) g_status[i] = 0ull;
}

// ---------------------------------------------------------------------------
// SpMM v3: TWO rows per warp, 2-way unrolled each -> 4 independent support
// gathers in flight. fp16 gathers (256B/row), fp32 accumulate, float4 stores.
// ---------------------------------------------------------------------------
__device__ __forceinline__ void acc_edge(float4& acc, int2 ed, int lane) {
    const float v = __int_as_float(ed.y);
    uint2 h = *reinterpret_cast<const uint2*>(
        &g_supph[(size_t)ed.x * D + lane * 4]);
    float2 a = __half22float2(*reinterpret_cast<__half2*>(&h.x));
    float2 q = __half22float2(*reinterpret_cast<__half2*>(&h.y));
    acc.x += a.x * v; acc.y += a.y * v;
    acc.z += q.x * v; acc.w += q.y * v;
}

__global__ __launch_bounds__(256) void spmm_kernel(float* __restrict__ out) {
    const int wid  = (blockIdx.x * blockDim.x + threadIdx.x) >> 5;
    const int lane = threadIdx.x & 31;
    const int rowA = wid * 2;
    const int rowB = rowA + 1;                 // N_NODES even -> always valid
    if (rowA >= N_NODES) return;

    int sA = __ldg(&g_rowstart[rowA]);
    const int eA = __ldg(&g_rowstart[rowA + 1]);
    int sB = eA;                               // rowstart[rowB] == eA (CSR)
    const int eB = __ldg(&g_rowstart[rowB + 1]);

    float4 accA = make_float4(0.f, 0.f, 0.f, 0.f);
    float4 accB = make_float4(0.f, 0.f, 0.f, 0.f);

    // interleaved main loop: 2 edges per row per iter -> 4 gathers in flight
    while (sA + 1 < eA && sB + 1 < eB) {
        int2 a0 = __ldg(&g_edge[sA]);
        int2 a1 = __ldg(&g_edge[sA + 1]);
        int2 b0 = __ldg(&g_edge[sB]);
        int2 b1 = __ldg(&g_edge[sB + 1]);
        acc_edge(accA, a0, lane);
        acc_edge(accB, b0, lane);
        acc_edge(accA, a1, lane);
        acc_edge(accB, b1, lane);
        sA += 2; sB += 2;
    }
    // drains
    for (; sA + 1 < eA; sA += 2) {
        int2 a0 = __ldg(&g_edge[sA]);
        int2 a1 = __ldg(&g_edge[sA + 1]);
        acc_edge(accA, a0, lane);
        acc_edge(accA, a1, lane);
    }
    if (sA < eA) acc_edge(accA, __ldg(&g_edge[sA]), lane);
    for (; sB + 1 < eB; sB += 2) {
        int2 b0 = __ldg(&g_edge[sB]);
        int2 b1 = __ldg(&g_edge[sB + 1]);
        acc_edge(accB, b0, lane);
        acc_edge(accB, b1, lane);
    }
    if (sB < eB) acc_edge(accB, __ldg(&g_edge[sB]), lane);

    reinterpret_cast<float4*>(out)[(size_t)rowA * (D / 4) + lane] = accA;
    reinterpret_cast<float4*>(out)[(size_t)rowB * (D / 4) + lane] = accB;
}

// ---------------------------------------------------------------------------
// Launch. Inputs: x, rows, cols, vals, W, b.  Output: f32 [N_NODES, D].
// Fork-join: 3-kernel CSR chain on side stream || pipelined GEMM on capture
// stream; join; SpMM.
// ---------------------------------------------------------------------------
extern "C" void kernel_launch(void* const* d_in, const int* in_sizes, int n_in,
                              void* d_out, int out_size) {
    const float* x    = (const float*)d_in[0];
    const int*   rows = (const int*)d_in[1];
    const int*   cols = (const int*)d_in[2];
    const float* vals = (const float*)d_in[3];
    const float* W    = (const float*)d_in[4];
    const float* b    = (const float*)d_in[5];
    float* out = (float*)d_out;

    cudaEventRecord(g_si.ev_fork, 0);
    cudaStreamWaitEvent(g_si.s2, g_si.ev_fork, 0);

    // --- CSR build chain on side stream (3 kernels, vectorized) ---
    {
        int n4 = N_EDGES / 4;
        hist_kernel<<<(n4 + 255) / 256, 256, 0, g_si.s2>>>((const int4*)rows);
        scan_lookback_kernel<<<NB_SCAN, SCAN_BLK, 0, g_si.s2>>>();
        fill_kernel<<<(n4 + 255) / 256, 256, 0, g_si.s2>>>(
            (const int4*)rows, (const int4*)cols, (const float4*)vals);
    }
    cudaEventRecord(g_si.ev_join, g_si.s2);

    // --- GEMM on the capture stream (overlaps the chain) ---
    gemm_tc_kernel<<<(N_NODES + GR - 1) / GR, 256, GEMM_SMEM_BYTES>>>(x, W, b);

    // --- join, then SpMM (2 rows per warp) ---
    cudaStreamWaitEvent(0, g_si.ev_join, 0);
    {
        long long total_threads = (long long)(N_NODES / 2) * 32;
        int blk = 256;
        int grid = (int)((total_threads + blk - 1) / blk);
        spmm_kernel<<<grid, blk>>>(out);
    }
}